// round 11
// baseline (speedup 1.0000x reference)
#include <cuda_runtime.h>
#include <cuda_fp16.h>

// ============================================================================
// Intergrator_5952824672851  (CFD cell integrator, F=6M faces, C=4M cells)
//
// per cell c, faces f0,f1,f2 = cell_face[:,c], normals n_i = unv[c,i,:]:
//   de_i = (uv_i . n_i) * area_i          (w = a*uv; de = w.n)
//   loss[c] = sum_i de_i
//   A = sum_i uv_i * de_i = sum_i w_i * (de_i * inva_i)
//   P = sum_i (p_i*a_i) * n_i ;  D = sum_i fD_i
//   out[c] = rhs_coef[c] * (-A - P/rho[c]) + D
//
// R10 -> R11: random-gather footprint 96MB -> 72MB so the tables stay
// L2-resident (R10 measured ~410MB of table DRAM round-trip):
//   T1[f] = uint2 { h2(wx f16, wy f16), h2(q f16, inva f16) }   (48 MB)
//   T2[f] = uint  { h2(fDx f16, fDy f16) }                       (24 MB)
// 2 gather LDGs per face (ld.64 + ld.32). All-f16 payload: predicted
// rel_err ~5e-4 (gate 1e-3). Streams stay .cs, gathers .cg.
// ============================================================================

#define MAX_F 6000000

__device__ uint2        g_t1[MAX_F];   // 48 MB: {wx|wy, q|inva}
__device__ unsigned int g_t2[MAX_F];   // 24 MB: {fDx|fDy}
__device__ int          g_idx_kind;    // 0 = int64, 1 = int32, 2 = float32

__device__ __forceinline__ unsigned pack_h2(float lo, float hi) {
    __half2 h = __halves2half2(__float2half_rn(lo), __float2half_rn(hi));
    return (unsigned)__half_as_ushort(__low2half(h)) |
           ((unsigned)__half_as_ushort(__high2half(h)) << 16);
}
__device__ __forceinline__ float unpack_lo(unsigned v) {
    return __half2float(__ushort_as_half((unsigned short)(v & 0xFFFFu)));
}
__device__ __forceinline__ float unpack_hi(unsigned v) {
    return __half2float(__ushort_as_half((unsigned short)(v >> 16)));
}

__global__ void __launch_bounds__(256)
pack_faces_kernel(const float2* __restrict__ uv_face,
                  const float*  __restrict__ p_face,
                  const float2* __restrict__ flux_D,
                  const float*  __restrict__ face_area,
                  const unsigned int* __restrict__ idx_words,
                  long long nwords,
                  int F) {
    if (blockIdx.x == 0) {   // dtype detection, single uniform barrier
        __shared__ unsigned s_oz[4], s_sm[4];
        int t = threadIdx.x;
        if (t < 128) {
            long long stride = nwords / 128;
            if (stride < 2) stride = 2;
            long long pos = stride * (long long)t;
            bool odd_zero = true, small = true;
            if (pos + 1 < nwords) {
                unsigned int lo = idx_words[pos & ~1LL];
                unsigned int hi = idx_words[pos | 1LL];
                odd_zero = (hi == 0u);
                small    = (lo < (1u << 24)) && (hi < (1u << 24) || hi == 0u);
            }
            unsigned all_oz = __ballot_sync(0xFFFFFFFFu, odd_zero);
            unsigned all_sm = __ballot_sync(0xFFFFFFFFu, small);
            if ((t & 31) == 0) { s_oz[t >> 5] = all_oz; s_sm[t >> 5] = all_sm; }
        }
        __syncthreads();
        if (t == 0) {
            bool oz = (s_oz[0] & s_oz[1] & s_oz[2] & s_oz[3]) == 0xFFFFFFFFu;
            bool sm = (s_sm[0] & s_sm[1] & s_sm[2] & s_sm[3]) == 0xFFFFFFFFu;
            g_idx_kind = oz ? 0 : (sm ? 1 : 2);
        }
    }

    int f = blockIdx.x * blockDim.x + threadIdx.x;
    if (f >= F) return;
    float2 uv = __ldcs(&uv_face[f]);
    float2 fd = __ldcs(&flux_D[f]);
    float  p  = __ldcs(&p_face[f]);
    float  a  = __ldcs(&face_area[f]);

    float wx   = a * uv.x;
    float wy   = a * uv.y;
    float q    = p * a;
    float inva = fminf(1.0f / fmaxf(a, 1e-30f), 60000.0f);  // f16-safe clamp

    g_t1[f] = make_uint2(pack_h2(wx, wy), pack_h2(q, inva));  // normal priority
    g_t2[f] = pack_h2(fd.x, fd.y);
}

__device__ __forceinline__ long long clampF(long long v, long long F) {
    if (v < 0) v = 0;
    if (v >= F) v = F - 1;
    return v;
}

__device__ __forceinline__ long long load_idx_cs(const void* p, int kind, long long i) {
    if (kind == 0) return __ldcs(&((const long long*)p)[i]);
    if (kind == 1) return (long long)__ldcs(&((const int*)p)[i]);
    return (long long)__ldcs(&((const float*)p)[i]);
}

__global__ void __launch_bounds__(256)
cell_integrate_kernel(const void*   __restrict__ cell_face, // [3, C]
                      const float2* __restrict__ unv,       // [C,3,2]
                      const float*  __restrict__ rho,       // [C]
                      const float*  __restrict__ rhs_coef,  // [C]
                      float*        __restrict__ out,       // [3C]
                      int C, int F) {
    int c = blockIdx.x * blockDim.x + threadIdx.x;
    if (c >= C) return;

    int kind = g_idx_kind;

    long long f0 = clampF(load_idx_cs(cell_face, kind, c), F);
    long long f1 = clampF(load_idx_cs(cell_face, kind, (long long)C + c), F);
    long long f2 = clampF(load_idx_cs(cell_face, kind, 2LL * C + c), F);

    // 6 gather LDGs (3x ld.64 + 3x ld.32), all independent, L2-resident tables
    uint2    t0 = __ldcg(&g_t1[f0]);
    uint2    t1 = __ldcg(&g_t1[f1]);
    uint2    t2 = __ldcg(&g_t1[f2]);
    unsigned d0 = __ldcg(&g_t2[f0]);
    unsigned d1 = __ldcg(&g_t2[f1]);
    unsigned d2 = __ldcg(&g_t2[f2]);

    float2 n0 = __ldcs(&unv[3 * c + 0]);
    float2 n1 = __ldcs(&unv[3 * c + 1]);
    float2 n2 = __ldcs(&unv[3 * c + 2]);

    float wx0 = unpack_lo(t0.x), wy0 = unpack_hi(t0.x);
    float wx1 = unpack_lo(t1.x), wy1 = unpack_hi(t1.x);
    float wx2 = unpack_lo(t2.x), wy2 = unpack_hi(t2.x);
    float q0 = unpack_lo(t0.y), ia0 = unpack_hi(t0.y);
    float q1 = unpack_lo(t1.y), ia1 = unpack_hi(t1.y);
    float q2 = unpack_lo(t2.y), ia2 = unpack_hi(t2.y);

    float de0 = wx0 * n0.x + wy0 * n0.y;
    float de1 = wx1 * n1.x + wy1 * n1.y;
    float de2 = wx2 * n2.x + wy2 * n2.y;

    float loss = de0 + de1 + de2;

    float s0 = de0 * ia0;
    float s1 = de1 * ia1;
    float s2 = de2 * ia2;

    float Ax = wx0 * s0 + wx1 * s1 + wx2 * s2;   // w*inva = uv
    float Ay = wy0 * s0 + wy1 * s1 + wy2 * s2;

    float Px = q0 * n0.x + q1 * n1.x + q2 * n2.x;
    float Py = q0 * n0.y + q1 * n1.y + q2 * n2.y;

    float Dx = unpack_lo(d0) + unpack_lo(d1) + unpack_lo(d2);
    float Dy = unpack_hi(d0) + unpack_hi(d1) + unpack_hi(d2);

    float inv_rho = 1.0f / __ldcs(&rho[c]);
    float rc = __ldcs(&rhs_coef[c]);

    float ox = rc * (-Ax - inv_rho * Px) + Dx;
    float oy = rc * (-Ay - inv_rho * Py) + Dy;

    __stcs(&out[c], loss);                             // loss_continuity [C,1]
    float2* o2 = reinterpret_cast<float2*>(out + C);
    __stcs(&o2[c], make_float2(ox, oy));               // out [C,2]
}

extern "C" void kernel_launch(void* const* d_in, const int* in_sizes, int n_in,
                              void* d_out, int out_size) {
    // 0 uv_face [F,2] f32 | 1 p_face [F,1] f32 | 2 flux_D [F,2] f32
    // 3 unv [C,3,2] f32   | 4 rho [C,1] f32    | 5 rhs_coef [C,1] f32
    // 6 face_area [F,1] f32 | 7 cell_face [3,C] (int64 or downcast)
    const float2* uv_face   = (const float2*)d_in[0];
    const float*  p_face    = (const float*) d_in[1];
    const float2* flux_D    = (const float2*)d_in[2];
    const float2* unv       = (const float2*)d_in[3];
    const float*  rho       = (const float*) d_in[4];
    const float*  rhs_coef  = (const float*) d_in[5];
    const float*  face_area = (const float*) d_in[6];
    const void*   cell_face = d_in[7];

    int F = in_sizes[1];   // p_face element count
    int C = in_sizes[4];   // rho element count
    float* out = (float*)d_out;

    long long nwords = 3LL * C;

    const int TPB = 256;
    pack_faces_kernel<<<(F + TPB - 1) / TPB, TPB>>>(uv_face, p_face, flux_D, face_area,
                                                    (const unsigned int*)cell_face,
                                                    nwords, F);
    cell_integrate_kernel<<<(C + TPB - 1) / TPB, TPB>>>(cell_face, unv, rho, rhs_coef,
                                                        out, C, F);
}

// round 13
// speedup vs baseline: 1.0007x; 1.0007x over previous
#include <cuda_runtime.h>
#include <cuda_fp16.h>

// ============================================================================
// Intergrator_5952824672851  (CFD cell integrator, F=6M faces, C=4M cells)
//
// per cell c, faces f0,f1,f2 = cell_face[:,c], normals n_i = unv[c,i,:]:
//   de_i = (uv_i . n_i) * area_i          (w = a*uv; de = w.n, fp32-exact)
//   loss[c] = sum_i de_i
//   A = sum_i w_i * (de_i * inva_i) ; P = sum_i (p_i*a_i)*n_i ; D = sum_i fD_i
//   out[c] = rhs_coef[c] * (-A - P/rho[c]) + D
//
// R12 -> R13: same evict-last theory, fixed PTX encoding. ptxas rejects the
// immediate .L2::evict_last qualifier on 128-bit ld/st; use the
// createpolicy.fractional.L2::evict_last + ld/st.global.L2::cache_hint form
// instead (supported on all widths, sm_80+).
// Record: { wx=a*u f32, wy=a*v f32, h2(q=p*a, inva=1/a), h2(fDx, fDy) } =16B.
// Streams stay .cs; gathers + table stores carry the evict-last policy.
// ============================================================================

#define MAX_F 6000000

__device__ float4 g_rec[MAX_F];   // 96 MB table, one 32B-sector touch per gather
__device__ int    g_idx_kind;     // 0 = int64, 1 = int32, 2 = float32

__device__ __forceinline__ unsigned pack_h2(float lo, float hi) {
    __half2 h = __halves2half2(__float2half_rn(lo), __float2half_rn(hi));
    return (unsigned)__half_as_ushort(__low2half(h)) |
           ((unsigned)__half_as_ushort(__high2half(h)) << 16);
}
__device__ __forceinline__ float unpack_lo(unsigned v) {
    return __half2float(__ushort_as_half((unsigned short)(v & 0xFFFFu)));
}
__device__ __forceinline__ float unpack_hi(unsigned v) {
    return __half2float(__ushort_as_half((unsigned short)(v >> 16)));
}

// 64-bit access policy: all table lines -> L2 evict_last
__device__ __forceinline__ unsigned long long make_evict_last_policy() {
    unsigned long long pol;
    asm("createpolicy.fractional.L2::evict_last.b64 %0, 1.0;" : "=l"(pol));
    return pol;
}
__device__ __forceinline__ float4 ldg_policy(const float4* p, unsigned long long pol) {
    float4 v;
    asm volatile("ld.global.L2::cache_hint.v4.f32 {%0,%1,%2,%3}, [%4], %5;"
                 : "=f"(v.x), "=f"(v.y), "=f"(v.z), "=f"(v.w)
                 : "l"(p), "l"(pol));
    return v;
}
__device__ __forceinline__ void stg_policy(float4* p, float4 v, unsigned long long pol) {
    asm volatile("st.global.L2::cache_hint.v4.f32 [%0], {%1,%2,%3,%4}, %5;"
                 :: "l"(p), "f"(v.x), "f"(v.y), "f"(v.z), "f"(v.w), "l"(pol)
                 : "memory");
}

__global__ void __launch_bounds__(256)
pack_faces_kernel(const float2* __restrict__ uv_face,
                  const float*  __restrict__ p_face,
                  const float2* __restrict__ flux_D,
                  const float*  __restrict__ face_area,
                  const unsigned int* __restrict__ idx_words,
                  long long nwords,
                  int F) {
    if (blockIdx.x == 0) {   // dtype detection, single uniform barrier
        __shared__ unsigned s_oz[4], s_sm[4];
        int t = threadIdx.x;
        if (t < 128) {
            long long stride = nwords / 128;
            if (stride < 2) stride = 2;
            long long pos = stride * (long long)t;
            bool odd_zero = true, small = true;
            if (pos + 1 < nwords) {
                unsigned int lo = idx_words[pos & ~1LL];
                unsigned int hi = idx_words[pos | 1LL];
                odd_zero = (hi == 0u);
                small    = (lo < (1u << 24)) && (hi < (1u << 24) || hi == 0u);
            }
            unsigned all_oz = __ballot_sync(0xFFFFFFFFu, odd_zero);
            unsigned all_sm = __ballot_sync(0xFFFFFFFFu, small);
            if ((t & 31) == 0) { s_oz[t >> 5] = all_oz; s_sm[t >> 5] = all_sm; }
        }
        __syncthreads();
        if (t == 0) {
            bool oz = (s_oz[0] & s_oz[1] & s_oz[2] & s_oz[3]) == 0xFFFFFFFFu;
            bool sm = (s_sm[0] & s_sm[1] & s_sm[2] & s_sm[3]) == 0xFFFFFFFFu;
            g_idx_kind = oz ? 0 : (sm ? 1 : 2);
        }
    }

    int f = blockIdx.x * blockDim.x + threadIdx.x;
    if (f >= F) return;
    float2 uv = __ldcs(&uv_face[f]);
    float2 fd = __ldcs(&flux_D[f]);
    float  p  = __ldcs(&p_face[f]);
    float  a  = __ldcs(&face_area[f]);

    float4 rec;
    rec.x = a * uv.x;
    rec.y = a * uv.y;
    rec.z = __uint_as_float(pack_h2(p * a, fminf(1.0f / fmaxf(a, 1e-30f), 60000.0f)));
    rec.w = __uint_as_float(pack_h2(fd.x, fd.y));

    unsigned long long pol = make_evict_last_policy();
    stg_policy(&g_rec[f], rec, pol);     // table lines: L2 evict-LAST
}

__device__ __forceinline__ long long clampF(long long v, long long F) {
    if (v < 0) v = 0;
    if (v >= F) v = F - 1;
    return v;
}

__device__ __forceinline__ long long load_idx_cs(const void* p, int kind, long long i) {
    if (kind == 0) return __ldcs(&((const long long*)p)[i]);
    if (kind == 1) return (long long)__ldcs(&((const int*)p)[i]);
    return (long long)__ldcs(&((const float*)p)[i]);
}

__global__ void __launch_bounds__(256)
cell_integrate_kernel(const void*   __restrict__ cell_face, // [3, C]
                      const float2* __restrict__ unv,       // [C,3,2]
                      const float*  __restrict__ rho,       // [C]
                      const float*  __restrict__ rhs_coef,  // [C]
                      float*        __restrict__ out,       // [3C]
                      int C, int F) {
    int c = blockIdx.x * blockDim.x + threadIdx.x;
    if (c >= C) return;

    int kind = g_idx_kind;

    long long f0 = clampF(load_idx_cs(cell_face, kind, c), F);
    long long f1 = clampF(load_idx_cs(cell_face, kind, (long long)C + c), F);
    long long f2 = clampF(load_idx_cs(cell_face, kind, 2LL * C + c), F);

    // 3 random gathers, one 32B sector each, L2 evict-last (resident table)
    unsigned long long pol = make_evict_last_policy();
    float4 r0 = ldg_policy(&g_rec[f0], pol);
    float4 r1 = ldg_policy(&g_rec[f1], pol);
    float4 r2 = ldg_policy(&g_rec[f2], pol);

    float2 n0 = __ldcs(&unv[3 * c + 0]);
    float2 n1 = __ldcs(&unv[3 * c + 1]);
    float2 n2 = __ldcs(&unv[3 * c + 2]);

    unsigned z0 = __float_as_uint(r0.z), w0 = __float_as_uint(r0.w);
    unsigned z1 = __float_as_uint(r1.z), w1 = __float_as_uint(r1.w);
    unsigned z2 = __float_as_uint(r2.z), w2 = __float_as_uint(r2.w);

    float de0 = r0.x * n0.x + r0.y * n0.y;
    float de1 = r1.x * n1.x + r1.y * n1.y;
    float de2 = r2.x * n2.x + r2.y * n2.y;

    float loss = de0 + de1 + de2;

    float s0 = de0 * unpack_hi(z0);    // de * (1/area)
    float s1 = de1 * unpack_hi(z1);
    float s2 = de2 * unpack_hi(z2);

    float Ax = r0.x * s0 + r1.x * s1 + r2.x * s2;   // w*inva = uv
    float Ay = r0.y * s0 + r1.y * s1 + r2.y * s2;

    float q0 = unpack_lo(z0), q1 = unpack_lo(z1), q2 = unpack_lo(z2);
    float Px = q0 * n0.x + q1 * n1.x + q2 * n2.x;
    float Py = q0 * n0.y + q1 * n1.y + q2 * n2.y;

    float Dx = unpack_lo(w0) + unpack_lo(w1) + unpack_lo(w2);
    float Dy = unpack_hi(w0) + unpack_hi(w1) + unpack_hi(w2);

    float inv_rho = 1.0f / __ldcs(&rho[c]);
    float rc = __ldcs(&rhs_coef[c]);

    float ox = rc * (-Ax - inv_rho * Px) + Dx;
    float oy = rc * (-Ay - inv_rho * Py) + Dy;

    __stcs(&out[c], loss);                             // loss_continuity [C,1]
    float2* o2 = reinterpret_cast<float2*>(out + C);
    __stcs(&o2[c], make_float2(ox, oy));               // out [C,2]
}

extern "C" void kernel_launch(void* const* d_in, const int* in_sizes, int n_in,
                              void* d_out, int out_size) {
    // 0 uv_face [F,2] f32 | 1 p_face [F,1] f32 | 2 flux_D [F,2] f32
    // 3 unv [C,3,2] f32   | 4 rho [C,1] f32    | 5 rhs_coef [C,1] f32
    // 6 face_area [F,1] f32 | 7 cell_face [3,C] (int64 or downcast)
    const float2* uv_face   = (const float2*)d_in[0];
    const float*  p_face    = (const float*) d_in[1];
    const float2* flux_D    = (const float2*)d_in[2];
    const float2* unv       = (const float2*)d_in[3];
    const float*  rho       = (const float*) d_in[4];
    const float*  rhs_coef  = (const float*) d_in[5];
    const float*  face_area = (const float*) d_in[6];
    const void*   cell_face = d_in[7];

    int F = in_sizes[1];   // p_face element count
    int C = in_sizes[4];   // rho element count
    float* out = (float*)d_out;

    long long nwords = 3LL * C;

    const int TPB = 256;
    pack_faces_kernel<<<(F + TPB - 1) / TPB, TPB>>>(uv_face, p_face, flux_D, face_area,
                                                    (const unsigned int*)cell_face,
                                                    nwords, F);
    cell_integrate_kernel<<<(C + TPB - 1) / TPB, TPB>>>(cell_face, unv, rho, rhs_coef,
                                                        out, C, F);
}